// round 12
// baseline (speedup 1.0000x reference)
#include <cuda_runtime.h>
#include <cstdint>

// Problem constants
#define HDIM   1024
#define DIN    256
#define DOUT   256
#define BATCH  8192
#define NLAYERS 64
#define BK     32

// Scratch (device globals; allocation-free):
__device__ float g_act[2][HDIM * BATCH];                     // activations, m = 2h-1 form, [H, B]
__device__ float g_xm[DIN * BATCH];                          // 2x-1, [DIN, B]
__device__ float g_wt[(size_t)NLAYERS * HDIM * HDIM];        // W transposed: [l][k][m]
__device__ float g_et[(size_t)DIN * HDIM];                   // E transposed: [k][m]
__device__ float g_ct[(size_t)HDIM * DOUT];                  // C transposed: [k][m]

enum { MODE_EXP = 0, MODE_HID = 1, MODE_OUT = 2 };

typedef unsigned long long u64;

__device__ __forceinline__ u64 pack2(float lo, float hi) {
    u64 r;
    asm("mov.b64 %0, {%1, %2};" : "=l"(r) : "f"(lo), "f"(hi));
    return r;
}
__device__ __forceinline__ void unpack2(u64 v, float& lo, float& hi) {
    asm("mov.b64 {%0, %1}, %2;" : "=f"(lo), "=f"(hi) : "l"(v));
}
__device__ __forceinline__ u64 fma2(u64 a, u64 b, u64 c) {
    u64 d;
    asm("fma.rn.f32x2 %0, %1, %2, %3;" : "=l"(d) : "l"(a), "l"(b), "l"(c));
    return d;
}
__device__ __forceinline__ void cp16(uint32_t dst, const float* src) {
    asm volatile("cp.async.cg.shared.global [%0], [%1], 16;" :: "r"(dst), "l"(src));
}
__device__ __forceinline__ void cp_commit() {
    asm volatile("cp.async.commit_group;");
}
template <int N>
__device__ __forceinline__ void cp_wait() {
    asm volatile("cp.async.wait_group %0;" :: "n"(N));
}

// ---------------- pre-pass kernels ----------------
__global__ void affine_kernel(const float* __restrict__ x, float* __restrict__ xm) {
    int i = blockIdx.x * blockDim.x + threadIdx.x;
    float4 v = ((const float4*)x)[i];
    v.x = 2.0f * v.x - 1.0f; v.y = 2.0f * v.y - 1.0f;
    v.z = 2.0f * v.z - 1.0f; v.w = 2.0f * v.w - 1.0f;
    ((float4*)xm)[i] = v;
}

__global__ void transpose_kernel(const float* __restrict__ in, float* __restrict__ out,
                                 int R, int Cc) {
    __shared__ float t[32][33];
    const size_t off = (size_t)blockIdx.z * R * Cc;
    in += off; out += off;
    int c0 = blockIdx.x * 32, r0 = blockIdx.y * 32;
    int lx = threadIdx.x, ly = threadIdx.y;
    #pragma unroll
    for (int i = 0; i < 32; i += 8)
        t[ly + i][lx] = in[(size_t)(r0 + ly + i) * Cc + c0 + lx];
    __syncthreads();
    #pragma unroll
    for (int i = 0; i < 32; i += 8)
        out[(size_t)(c0 + ly + i) * R + r0 + lx] = t[lx][ly + i];
}

// ---------------- main GEMM ----------------
// At: [K, M] (transposed weights). Bm: [K, N]. C: [M, N].
#define STG_FLOATS (BK * 128)                 // per matrix per stage
#define SMEM_BYTES (3 * STG_FLOATS * 2 * 4)   // 3 stages, A+B

template <int MODE>
__global__ __launch_bounds__(256, 2)
void gemm_kernel(const float* __restrict__ At, const float* __restrict__ Bm,
                 float* __restrict__ C, int M, int N, int K)
{
    extern __shared__ float smem[];
    constexpr int TM = 8;
    // layout: As stages [0..3), Bs stages [3..6) in units of STG_FLOATS
    const int tid = threadIdx.x;
    const int m0 = blockIdx.y * 128;
    const int n0 = blockIdx.x * 128;
    const int tx = tid & 15;
    const int ty = tid >> 4;

    // loader coords: BK*128 floats = 1024 chunks of 16B; 4 per thread per matrix
    const int l_row = tid >> 5;                               // 0..7 (+8,+16,+24)
    const int l_q   = tid & 31;
    const int a_col = l_q * 4;
    const int b_pos = ((l_q & 1) << 6) | ((l_q >> 1) << 2);   // quad swizzle

    u64 acc2[TM][4];
    #pragma unroll
    for (int i = 0; i < TM; i++)
        #pragma unroll
        for (int jp = 0; jp < 4; jp++) acc2[i][jp] = 0ull;

    const int ntiles = K / BK;

    auto load_tile = [&](int s, int t) {
        const int kb = t * BK;
        float* As = smem + s * STG_FLOATS;
        float* Bs = smem + (3 + s) * STG_FLOATS;
        #pragma unroll
        for (int it = 0; it < 4; it++) {
            const int r = l_row + it * 8;
            cp16((uint32_t)__cvta_generic_to_shared(As + r * 128 + a_col),
                 At + (size_t)(kb + r) * M + m0 + a_col);
            cp16((uint32_t)__cvta_generic_to_shared(Bs + r * 128 + b_pos),
                 Bm + (size_t)(kb + r) * N + n0 + l_q * 4);
        }
        cp_commit();
    };

    load_tile(0, 0);
    load_tile(1, 1);

    for (int t = 0; t < ntiles; t++) {
        cp_wait<1>();
        __syncthreads();   // also protects stage (t+2)%3 == (t-1)%3 overwrite

        if (t + 2 < ntiles) load_tile((t + 2) % 3, t + 2);
        else cp_commit();

        const float* As = smem + (t % 3) * STG_FLOATS;
        const float* Bs = smem + (3 + (t % 3)) * STG_FLOATS;

        // fragment double-buffer over k
        float a[2][TM];
        u64 bp[2][4];
        {
            *(float4*)&a[0][0] = *(const float4*)&As[ty * TM];
            *(float4*)&a[0][4] = *(const float4*)&As[ty * TM + 4];
            const ulonglong2 b01 = *(const ulonglong2*)&Bs[tx * 4];
            const ulonglong2 b23 = *(const ulonglong2*)&Bs[64 + tx * 4];
            bp[0][0] = b01.x; bp[0][1] = b01.y; bp[0][2] = b23.x; bp[0][3] = b23.y;
        }

        #pragma unroll
        for (int k = 0; k < BK; k++) {
            const int curf = k & 1;
            const int nxtf = curf ^ 1;
            if (k + 1 < BK) {
                *(float4*)&a[nxtf][0] = *(const float4*)&As[(k + 1) * 128 + ty * TM];
                *(float4*)&a[nxtf][4] = *(const float4*)&As[(k + 1) * 128 + ty * TM + 4];
                const ulonglong2 b01 = *(const ulonglong2*)&Bs[(k + 1) * 128 + tx * 4];
                const ulonglong2 b23 = *(const ulonglong2*)&Bs[(k + 1) * 128 + 64 + tx * 4];
                bp[nxtf][0] = b01.x; bp[nxtf][1] = b01.y;
                bp[nxtf][2] = b23.x; bp[nxtf][3] = b23.y;
            }
            #pragma unroll
            for (int i = 0; i < TM; i++) {
                const u64 aa = pack2(a[curf][i], a[curf][i]);
                #pragma unroll
                for (int jp = 0; jp < 4; jp++)
                    acc2[i][jp] = fma2(aa, bp[curf][jp], acc2[i][jp]);
            }
        }
    }

    // ---- epilogue ----
    #pragma unroll
    for (int i = 0; i < TM; i++) {
        const int row = m0 + ty * TM + i;
        #pragma unroll
        for (int j4 = 0; j4 < 2; j4++) {
            const int col = n0 + tx * 8 + j4 * 4;
            float y[4];
            unpack2(acc2[i][j4 * 2 + 0], y[0], y[1]);
            unpack2(acc2[i][j4 * 2 + 1], y[2], y[3]);
            if (MODE == MODE_HID) {
                float4 r = *(const float4*)(Bm + (size_t)row * N + col);
                y[0] += r.x; y[1] += r.y; y[2] += r.z; y[3] += r.w;
            }
            float4 o;
            #pragma unroll
            for (int q = 0; q < 4; q++) {
                float v = fminf(fmaxf(y[q], 0.0f), 1.0f);
                if (MODE != MODE_OUT) v = 2.0f * v - 1.0f;
                ((float*)&o)[q] = v;
            }
            *(float4*)(C + (size_t)row * N + col) = o;
        }
    }
}

extern "C" void kernel_launch(void* const* d_in, const int* in_sizes, int n_in,
                              void* d_out, int out_size)
{
    const float* x           = (const float*)d_in[0]; // [DIN, BATCH]
    const float* expansion   = (const float*)d_in[1]; // [HDIM, DIN]
    const float* hidden      = (const float*)d_in[2]; // [NLAYERS, HDIM, HDIM]
    const float* compression = (const float*)d_in[3]; // [DOUT, HDIM]
    float* out = (float*)d_out;                        // [DOUT, BATCH]

    float *act0, *xm, *wt, *et, *ct;
    cudaGetSymbolAddress((void**)&act0, g_act);
    cudaGetSymbolAddress((void**)&xm, g_xm);
    cudaGetSymbolAddress((void**)&wt, g_wt);
    cudaGetSymbolAddress((void**)&et, g_et);
    cudaGetSymbolAddress((void**)&ct, g_ct);
    float* act1 = act0 + (size_t)HDIM * BATCH;

    cudaFuncSetAttribute(gemm_kernel<MODE_EXP>, cudaFuncAttributeMaxDynamicSharedMemorySize, SMEM_BYTES);
    cudaFuncSetAttribute(gemm_kernel<MODE_HID>, cudaFuncAttributeMaxDynamicSharedMemorySize, SMEM_BYTES);
    cudaFuncSetAttribute(gemm_kernel<MODE_OUT>, cudaFuncAttributeMaxDynamicSharedMemorySize, SMEM_BYTES);

    // ---- pre-pass: affine input + transpose all weight matrices ----
    affine_kernel<<<(DIN * BATCH / 4) / 256, 256>>>(x, xm);
    transpose_kernel<<<dim3(DIN / 32, HDIM / 32, 1), dim3(32, 8)>>>(expansion, et, HDIM, DIN);
    transpose_kernel<<<dim3(HDIM / 32, HDIM / 32, NLAYERS), dim3(32, 8)>>>(hidden, wt, HDIM, HDIM);
    transpose_kernel<<<dim3(HDIM / 32, DOUT / 32, 1), dim3(32, 8)>>>(compression, ct, DOUT, HDIM);

    dim3 blk(256);

    // Expansion: m0 = 2*clip(E @ (2x-1)) - 1
    gemm_kernel<MODE_EXP><<<dim3(BATCH / 128, HDIM / 128), blk, SMEM_BYTES>>>(
        et, xm, act0, HDIM, BATCH, DIN);

    // 64 hidden layers: m' = 2*clip(W m + m) - 1
    float* cur = act0;
    float* nxt = act1;
    for (int l = 0; l < NLAYERS; l++) {
        gemm_kernel<MODE_HID><<<dim3(BATCH / 128, HDIM / 128), blk, SMEM_BYTES>>>(
            wt + (size_t)l * HDIM * HDIM, cur, nxt, HDIM, BATCH, HDIM);
        float* tmp = cur; cur = nxt; nxt = tmp;
    }

    // Compression: out = clip(Cmp @ m)
    gemm_kernel<MODE_OUT><<<dim3(BATCH / 128, DOUT / 128), blk, SMEM_BYTES>>>(
        ct, cur, out, DOUT, BATCH, HDIM);
}